// round 1
// baseline (speedup 1.0000x reference)
#include <cuda_runtime.h>
#include <cuda_bf16.h>
#include <cstdint>

// Problem constants
#define NNODES 30000
#define NEDGES 100000
#define HH 8
#define DKH 64
#define DIN 512
#define DOUT 512

// ---------------- device scratch (no cudaMalloc allowed) ----------------
__device__ float g_q   [(size_t)NNODES * 512];      // q projections of dst nodes
__device__ float g_kvt [(size_t)NNODES * 1024];     // [kt | vt] transformed projections of src nodes
__device__ float g_t   [(size_t)NNODES * 512];      // aggregated messages
__device__ float g_Wf  [512 * 1024];                // folded [Wk@A | Wv@M]
__device__ float g_bf  [1024];                      // folded biases
__device__ float g_att [(size_t)NEDGES * HH];       // per-edge att / exp values
__device__ float g_max [(size_t)NNODES * HH];
__device__ float g_sum [(size_t)NNODES * HH];

// ---------------- helpers ----------------
__device__ __forceinline__ void atomicMaxF(float* addr, float v) {
    if (v >= 0.f) atomicMax((int*)addr, __float_as_int(v));
    else          atomicMin((unsigned int*)addr, __float_as_uint(v));
}

// ---------------- fold kernel: Wf[i][j] = sum_k W[i][h*64+k] * T[h][k][d] ----------------
// grid: (1024/256, 513). Row i==512 folds the bias vectors instead.
__global__ void fold_kernel(const float* __restrict__ Wk, const float* __restrict__ bk,
                            const float* __restrict__ Wv, const float* __restrict__ bv,
                            const float* __restrict__ Arel, const float* __restrict__ Mrel,
                            float* __restrict__ Wf, float* __restrict__ bf)
{
    int j = blockIdx.x * blockDim.x + threadIdx.x;   // 0..1023
    int i = blockIdx.y;                              // 0..512 (512 == bias row)
    const float* T;
    int jj;
    const float* Wrow;
    if (j < 512) { T = Arel; jj = j; }
    else         { T = Mrel; jj = j - 512; }
    int h = jj >> 6, d = jj & 63;
    if (i < 512) {
        Wrow = (j < 512 ? Wk : Wv) + (size_t)i * 512 + h * 64;
    } else {
        Wrow = (j < 512 ? bk : bv) + h * 64;
    }
    const float* Tcol = T + (size_t)h * 64 * 64 + d; // stride 64 over k
    float s = 0.f;
#pragma unroll 8
    for (int k = 0; k < 64; k++) s += Wrow[k] * Tcol[k * 64];
    if (i < 512) Wf[(size_t)i * 1024 + j] = s;
    else         bf[j] = s;
}

// ---------------- SGEMM: C[M,LDB] = A[M,512] @ B[512,LDB] + bias, optional skip-blend ----------------
template<int LDB, bool BLEND>
__global__ __launch_bounds__(256)
void sgemm_kernel(const float* __restrict__ A, const float* __restrict__ B,
                  const float* __restrict__ bias, float* __restrict__ C,
                  const float* __restrict__ Hres, const float* __restrict__ skip,
                  int rel, int M)
{
    constexpr int BM = 128, BN = 128, BK = 16;
    __shared__ float As[BK][BM + 4];
    __shared__ float Bs[BK][BN];
    const int tid = threadIdx.x;
    const int m0 = blockIdx.y * BM;
    const int n0 = blockIdx.x * BN;

    float acc[8][8];
#pragma unroll
    for (int i = 0; i < 8; i++)
#pragma unroll
        for (int j = 0; j < 8; j++) acc[i][j] = 0.f;

    const int arow = tid >> 2;            // 0..63
    const int aq   = (tid & 3) * 4;       // 0,4,8,12
    const int brow = tid >> 5;            // 0..7
    const int bc   = (tid & 31) * 4;      // 0..124

    const int ty = tid >> 4, tx = tid & 15;

    for (int k0 = 0; k0 < 512; k0 += BK) {
#pragma unroll
        for (int rr = 0; rr < 2; rr++) {
            int r = arow + rr * 64;
            int gm = m0 + r;
            float4 a = (gm < M) ? *(const float4*)(A + (size_t)gm * 512 + k0 + aq)
                                : make_float4(0.f, 0.f, 0.f, 0.f);
            As[aq + 0][r] = a.x; As[aq + 1][r] = a.y;
            As[aq + 2][r] = a.z; As[aq + 3][r] = a.w;
        }
#pragma unroll
        for (int rr = 0; rr < 2; rr++) {
            int r = brow + rr * 8;
            *(float4*)(&Bs[r][bc]) = *(const float4*)(B + (size_t)(k0 + r) * LDB + n0 + bc);
        }
        __syncthreads();
#pragma unroll
        for (int k = 0; k < BK; k++) {
            float ra[8], rb[8];
            *(float4*)&ra[0] = *(const float4*)&As[k][ty * 8];
            *(float4*)&ra[4] = *(const float4*)&As[k][ty * 8 + 4];
            *(float4*)&rb[0] = *(const float4*)&Bs[k][tx * 8];
            *(float4*)&rb[4] = *(const float4*)&Bs[k][tx * 8 + 4];
#pragma unroll
            for (int i = 0; i < 8; i++)
#pragma unroll
                for (int j = 0; j < 8; j++)
                    acc[i][j] = fmaf(ra[i], rb[j], acc[i][j]);
        }
        __syncthreads();
    }

    float alpha = 1.f, beta = 0.f;
    if (BLEND) {
        float s = skip[rel];
        alpha = 1.f / (1.f + __expf(-s));
        beta  = 1.f - alpha;
    }
#pragma unroll
    for (int i = 0; i < 8; i++) {
        int gm = m0 + ty * 8 + i;
        if (gm >= M) break;
#pragma unroll
        for (int j = 0; j < 8; j += 4) {
            int gn = n0 + tx * 8 + j;
            float4 o;
            o.x = acc[i][j + 0] + bias[gn + 0];
            o.y = acc[i][j + 1] + bias[gn + 1];
            o.z = acc[i][j + 2] + bias[gn + 2];
            o.w = acc[i][j + 3] + bias[gn + 3];
            if (BLEND) {
                float4 hv = *(const float4*)(Hres + (size_t)gm * 512 + gn);
                o.x = o.x * alpha + hv.x * beta;
                o.y = o.y * alpha + hv.y * beta;
                o.z = o.z * alpha + hv.z * beta;
                o.w = o.w * alpha + hv.w * beta;
            }
            *(float4*)(C + (size_t)gm * LDB + gn) = o;
        }
    }
}

// ---------------- init of per-node max / sum ----------------
__global__ void init_ms_kernel(float* __restrict__ nmax, float* __restrict__ nsum, int n)
{
    int i = blockIdx.x * blockDim.x + threadIdx.x;
    if (i < n) { nmax[i] = __int_as_float(0xff800000); nsum[i] = 0.f; }
}

// ---------------- edge pass A: attention scores + segment max ----------------
// one warp per edge; lane -> (head h = lane/4, chunk g = lane%4 of 16 elems)
__global__ void edge_att_kernel(const float* __restrict__ q, const float* __restrict__ kvt,
                                const int* __restrict__ src, const int* __restrict__ dst,
                                const float* __restrict__ pri,
                                float* __restrict__ att, float* __restrict__ nmax, int E)
{
    int gid = blockIdx.x * blockDim.x + threadIdx.x;
    int e = gid >> 5;
    if (e >= E) return;
    int lane = gid & 31;
    int h = lane >> 2, g = lane & 3;
    int s = src[e], d = dst[e];
    const float4* qp = (const float4*)(q   + (size_t)d * 512  + h * 64 + g * 16);
    const float4* kp = (const float4*)(kvt + (size_t)s * 1024 + h * 64 + g * 16);
    float sum = 0.f;
#pragma unroll
    for (int t = 0; t < 4; t++) {
        float4 a = qp[t], b = kp[t];
        sum += a.x * b.x + a.y * b.y + a.z * b.z + a.w * b.w;
    }
    sum += __shfl_xor_sync(0xffffffffu, sum, 1);
    sum += __shfl_xor_sync(0xffffffffu, sum, 2);
    if (g == 0) {
        float a = sum * pri[h] * 0.125f;   // / sqrt(64)
        att[(size_t)e * HH + h] = a;
        atomicMaxF(&nmax[(size_t)d * HH + h], a);
    }
}

// ---------------- edge pass B: exp + segment sum ----------------
__global__ void edge_exp_kernel(const int* __restrict__ dst, float* __restrict__ att,
                                const float* __restrict__ nmax, float* __restrict__ nsum, int E)
{
    int i = blockIdx.x * blockDim.x + threadIdx.x;
    if (i >= E * HH) return;
    int e = i >> 3, h = i & 7;
    int d = dst[e];
    float ev = __expf(att[i] - nmax[(size_t)d * HH + h]);
    att[i] = ev;
    atomicAdd(&nsum[(size_t)d * HH + h], ev);
}

// ---------------- edge pass C: normalized weighted scatter of transformed values ----------------
__global__ void edge_scatter_kernel(const float* __restrict__ kvt,
                                    const int* __restrict__ src, const int* __restrict__ dst,
                                    const float* __restrict__ att, const float* __restrict__ nsum,
                                    float* __restrict__ tbuf, int E)
{
    int gid = blockIdx.x * blockDim.x + threadIdx.x;
    int e = gid >> 5;
    if (e >= E) return;
    int lane = gid & 31;
    int h = lane >> 2, g = lane & 3;
    int s = src[e], d = dst[e];
    float a = att[(size_t)e * HH + h] / nsum[(size_t)d * HH + h];
    const float4* vp = (const float4*)(kvt + (size_t)s * 1024 + 512 + h * 64 + g * 16);
    float* tp = tbuf + (size_t)d * 512 + h * 64 + g * 16;
#pragma unroll
    for (int t = 0; t < 4; t++) {
        float4 v = vp[t];
        atomicAdd(tp + t * 4 + 0, a * v.x);
        atomicAdd(tp + t * 4 + 1, a * v.y);
        atomicAdd(tp + t * 4 + 2, a * v.z);
        atomicAdd(tp + t * 4 + 3, a * v.w);
    }
}

// ---------------- host launcher ----------------
extern "C" void kernel_launch(void* const* d_in, const int* in_sizes, int n_in,
                              void* d_out, int out_size)
{
    const float* h_paper  = (const float*)d_in[0];
    const float* h_author = (const float*)d_in[1];
    const int*   src0     = (const int*)d_in[2];
    const int*   dst0     = (const int*)d_in[3];
    const int*   src1     = (const int*)d_in[4];
    const int*   dst1     = (const int*)d_in[5];
    // t=0: Wk0 bk0 Wq0 bq0 Wv0 bv0 Wa0 ba0 ; t=1: Wk1 bk1 Wq1 bq1 Wv1 bv1 Wa1 ba1
    const float* Wk0 = (const float*)d_in[6];  const float* bk0 = (const float*)d_in[7];
    const float* Wq0 = (const float*)d_in[8];  const float* bq0 = (const float*)d_in[9];
    const float* Wv0 = (const float*)d_in[10]; const float* bv0 = (const float*)d_in[11];
    const float* Wa0 = (const float*)d_in[12]; const float* ba0 = (const float*)d_in[13];
    const float* Wk1 = (const float*)d_in[14]; const float* bk1 = (const float*)d_in[15];
    const float* Wq1 = (const float*)d_in[16]; const float* bq1 = (const float*)d_in[17];
    const float* Wv1 = (const float*)d_in[18]; const float* bv1 = (const float*)d_in[19];
    const float* Wa1 = (const float*)d_in[20]; const float* ba1 = (const float*)d_in[21];
    const float* rel_att = (const float*)d_in[22]; // [2,8,64,64]
    const float* rel_msg = (const float*)d_in[23];
    const float* rel_pri = (const float*)d_in[24]; // [2,8]
    const float* skip    = (const float*)d_in[25]; // [2]

    const int N = in_sizes[0] / 512;
    const int E = in_sizes[2];
    float* out = (float*)d_out;

    void *p_q, *p_kvt, *p_t, *p_Wf, *p_bf, *p_att, *p_max, *p_sum;
    cudaGetSymbolAddress(&p_q,   g_q);
    cudaGetSymbolAddress(&p_kvt, g_kvt);
    cudaGetSymbolAddress(&p_t,   g_t);
    cudaGetSymbolAddress(&p_Wf,  g_Wf);
    cudaGetSymbolAddress(&p_bf,  g_bf);
    cudaGetSymbolAddress(&p_att, g_att);
    cudaGetSymbolAddress(&p_max, g_max);
    cudaGetSymbolAddress(&p_sum, g_sum);
    float* qbuf  = (float*)p_q;
    float* kvt   = (float*)p_kvt;
    float* tbuf  = (float*)p_t;
    float* Wf    = (float*)p_Wf;
    float* bf    = (float*)p_bf;
    float* attb  = (float*)p_att;
    float* nmax  = (float*)p_max;
    float* nsum  = (float*)p_sum;

    const int relstrideT = HH * DKH * DKH; // 8*64*64

    for (int rel = 0; rel < 2; rel++) {
        // relation 0: author->paper (src proj with type-1 weights, q with type-0)
        // relation 1: paper->author
        const float *Wk, *bk, *Wv, *bv, *Wq, *bq, *Wa, *ba;
        const float *hsrc, *hdst; const int *src, *dst;
        if (rel == 0) {
            Wk = Wk1; bk = bk1; Wv = Wv1; bv = bv1;
            Wq = Wq0; bq = bq0; Wa = Wa0; ba = ba0;
            hsrc = h_author; hdst = h_paper; src = src0; dst = dst0;
        } else {
            Wk = Wk0; bk = bk0; Wv = Wv0; bv = bv0;
            Wq = Wq1; bq = bq1; Wa = Wa1; ba = ba1;
            hsrc = h_paper; hdst = h_author; src = src1; dst = dst1;
        }
        const float* Arel = rel_att + (size_t)rel * relstrideT;
        const float* Mrel = rel_msg + (size_t)rel * relstrideT;
        const float* pri  = rel_pri + (size_t)rel * HH;
        float* outr = out + (size_t)rel * N * 512;

        // 1) fold relation transforms into weights
        fold_kernel<<<dim3(4, 513), 256>>>(Wk, bk, Wv, bv, Arel, Mrel, Wf, bf);

        // 2) kvt = h_src @ Wf + bf   ([N,1024])
        {
            dim3 grid(1024 / 128, (N + 127) / 128);
            sgemm_kernel<1024, false><<<grid, 256>>>(hsrc, Wf, bf, kvt, nullptr, nullptr, 0, N);
        }
        // 3) q = h_dst @ Wq + bq   ([N,512])
        {
            dim3 grid(512 / 128, (N + 127) / 128);
            sgemm_kernel<512, false><<<grid, 256>>>(hdst, Wq, bq, qbuf, nullptr, nullptr, 0, N);
        }
        // 4) init aggregation buffers
        cudaMemsetAsync(tbuf, 0, (size_t)N * 512 * sizeof(float));
        init_ms_kernel<<<(N * HH + 255) / 256, 256>>>(nmax, nsum, N * HH);

        // 5) edge attention + segment max
        edge_att_kernel<<<(E * 32 + 255) / 256, 256>>>(qbuf, kvt, src, dst, pri, attb, nmax, E);
        // 6) exp + segment sum
        edge_exp_kernel<<<(E * HH + 255) / 256, 256>>>(dst, attb, nmax, nsum, E);
        // 7) weighted scatter of values
        edge_scatter_kernel<<<(E * 32 + 255) / 256, 256>>>(kvt, src, dst, attb, nsum, tbuf, E);

        // 8) out = (t @ Wa + ba) * sigmoid(skip) + h_dst * (1 - sigmoid(skip))
        {
            dim3 grid(512 / 128, (N + 127) / 128);
            sgemm_kernel<512, true><<<grid, 256>>>(tbuf, Wa, ba, outr, hdst, skip, rel, N);
        }
    }
}

// round 2
// speedup vs baseline: 2.2710x; 2.2710x over previous
#include <cuda_runtime.h>
#include <cuda_bf16.h>
#include <cstdint>

// Problem constants
#define NNODES 30000
#define NEDGES 100000
#define HH 8
#define DKH 64

// ---------------- device scratch (no cudaMalloc allowed) ----------------
__device__ float g_q   [(size_t)NNODES * 512];      // q projections of dst nodes
__device__ float g_kvt [(size_t)NNODES * 1024];     // [kt | vt] transformed projections of src nodes
__device__ float g_t   [(size_t)NNODES * 512];      // aggregated messages
__device__ float g_Wf  [512 * 1024];                // folded [Wk@A | Wv@M]
__device__ float g_bf  [1024];                      // folded biases
__device__ float g_att [(size_t)NEDGES * HH];       // per-edge att / exp values
__device__ float g_max [(size_t)NNODES * HH];
__device__ float g_sum [(size_t)NNODES * HH];

// ---------------- helpers ----------------
__device__ __forceinline__ void atomicMaxF(float* addr, float v) {
    if (v >= 0.f) atomicMax((int*)addr, __float_as_int(v));
    else          atomicMin((unsigned int*)addr, __float_as_uint(v));
}

__device__ __forceinline__ uint32_t f2tf(float f) {
    uint32_t r;
    asm("cvt.rna.tf32.f32 %0, %1;" : "=r"(r) : "f"(f));
    return r;
}

__device__ __forceinline__ void mma_tf32(float* c, const uint32_t* a, const uint32_t* b) {
    asm volatile(
        "mma.sync.aligned.m16n8k8.row.col.f32.tf32.tf32.f32 "
        "{%0,%1,%2,%3}, {%4,%5,%6,%7}, {%8,%9}, {%0,%1,%2,%3};"
        : "+f"(c[0]), "+f"(c[1]), "+f"(c[2]), "+f"(c[3])
        : "r"(a[0]), "r"(a[1]), "r"(a[2]), "r"(a[3]), "r"(b[0]), "r"(b[1]));
}

// ---------------- fold kernel: Wf[i][j] = sum_k W[i][h*64+k] * T[h][k][d] ----------------
// grid: (1024/256, 513). Row i==512 folds the bias vectors instead.
__global__ void fold_kernel(const float* __restrict__ Wk, const float* __restrict__ bk,
                            const float* __restrict__ Wv, const float* __restrict__ bv,
                            const float* __restrict__ Arel, const float* __restrict__ Mrel,
                            float* __restrict__ Wf, float* __restrict__ bf)
{
    int j = blockIdx.x * blockDim.x + threadIdx.x;   // 0..1023
    int i = blockIdx.y;                              // 0..512 (512 == bias row)
    const float* T;
    int jj;
    const float* Wrow;
    if (j < 512) { T = Arel; jj = j; }
    else         { T = Mrel; jj = j - 512; }
    int h = jj >> 6, d = jj & 63;
    if (i < 512) {
        Wrow = (j < 512 ? Wk : Wv) + (size_t)i * 512 + h * 64;
    } else {
        Wrow = (j < 512 ? bk : bv) + h * 64;
    }
    const float* Tcol = T + (size_t)h * 64 * 64 + d; // stride 64 over k
    float s = 0.f;
#pragma unroll 8
    for (int k = 0; k < 64; k++) s += Wrow[k] * Tcol[k * 64];
    if (i < 512) Wf[(size_t)i * 1024 + j] = s;
    else         bf[j] = s;
}

// ---------------- tf32 tensor-core GEMM ----------------
// C[M,LDB] = A[M,512] @ B[512,LDB] + bias (optional sigmoid-skip blend with Hres)
// BM=128, BN=128, BK=32, 256 threads = 8 warps (2 M x 4 N), warp tile 64x32.
template<int LDB, bool BLEND>
__global__ __launch_bounds__(256)
void sgemm_tc(const float* __restrict__ A, const float* __restrict__ B,
              const float* __restrict__ bias, float* __restrict__ C,
              const float* __restrict__ Hres, const float* __restrict__ skip,
              int rel, int M)
{
    // padded smem layouts, tf32 bits stored as u32
    __shared__ uint32_t As[128 * 36];   // [m][k] stride 36
    __shared__ uint32_t Bs[32 * 136];   // [k][n] stride 136

    const int tid = threadIdx.x;
    const int m0 = blockIdx.y * 128;
    const int n0 = blockIdx.x * 128;

    const int ar = tid >> 3;            // 0..31 (A row group)
    const int ac = (tid & 7) * 4;       // k offset 0..28
    const int br = tid >> 5;            // 0..7  (B k group)
    const int bc = (tid & 31) * 4;      // n offset 0..124

    const int wid = tid >> 5, lane = tid & 31;
    const int wm = wid & 1, wn = wid >> 1;
    const int g = lane >> 2, t = lane & 3;

    float acc[4][4][4];
#pragma unroll
    for (int i = 0; i < 4; i++)
#pragma unroll
        for (int j = 0; j < 4; j++)
#pragma unroll
            for (int r = 0; r < 4; r++) acc[i][j][r] = 0.f;

    float4 areg[4], breg[4];

    // prefetch tile 0
#pragma unroll
    for (int r = 0; r < 4; r++) {
        int gm = m0 + ar + 32 * r;
        areg[r] = (gm < M) ? *(const float4*)(A + (size_t)gm * 512 + ac)
                           : make_float4(0.f, 0.f, 0.f, 0.f);
        breg[r] = *(const float4*)(B + (size_t)(br + 8 * r) * LDB + n0 + bc);
    }

    for (int it = 0; it < 16; ++it) {
        // stage current tile to smem (round to tf32 here)
#pragma unroll
        for (int r = 0; r < 4; r++) {
            uint4 ua = make_uint4(f2tf(areg[r].x), f2tf(areg[r].y), f2tf(areg[r].z), f2tf(areg[r].w));
            *(uint4*)&As[(ar + 32 * r) * 36 + ac] = ua;
            uint4 ub = make_uint4(f2tf(breg[r].x), f2tf(breg[r].y), f2tf(breg[r].z), f2tf(breg[r].w));
            *(uint4*)&Bs[(br + 8 * r) * 136 + bc] = ub;
        }
        __syncthreads();

        // prefetch next tile
        if (it + 1 < 16) {
            int k0 = (it + 1) * 32;
#pragma unroll
            for (int r = 0; r < 4; r++) {
                int gm = m0 + ar + 32 * r;
                areg[r] = (gm < M) ? *(const float4*)(A + (size_t)gm * 512 + k0 + ac)
                                   : make_float4(0.f, 0.f, 0.f, 0.f);
                breg[r] = *(const float4*)(B + (size_t)(k0 + br + 8 * r) * LDB + n0 + bc);
            }
        }

        // compute on staged tile
#pragma unroll
        for (int s = 0; s < 4; s++) {
            uint32_t af[4][4];
#pragma unroll
            for (int i = 0; i < 4; i++) {
                int base = (wm * 64 + i * 16 + g) * 36 + 8 * s + t;
                af[i][0] = As[base];
                af[i][1] = As[base + 8 * 36];
                af[i][2] = As[base + 4];
                af[i][3] = As[base + 8 * 36 + 4];
            }
            uint32_t bfr[4][2];
#pragma unroll
            for (int j = 0; j < 4; j++) {
                int base = (8 * s + t) * 136 + wn * 32 + j * 8 + g;
                bfr[j][0] = Bs[base];
                bfr[j][1] = Bs[base + 4 * 136];
            }
#pragma unroll
            for (int i = 0; i < 4; i++)
#pragma unroll
                for (int j = 0; j < 4; j++)
                    mma_tf32(acc[i][j], af[i], bfr[j]);
        }
        __syncthreads();
    }

    // epilogue
    float alpha = 1.f, beta = 0.f;
    if (BLEND) {
        float s = skip[rel];
        alpha = 1.f / (1.f + __expf(-s));
        beta = 1.f - alpha;
    }
#pragma unroll
    for (int i = 0; i < 4; i++) {
        int row = m0 + wm * 64 + i * 16 + g;
#pragma unroll
        for (int j = 0; j < 4; j++) {
            int col = n0 + wn * 32 + j * 8 + 2 * t;
            float2 bv = *(const float2*)(bias + col);
#pragma unroll
            for (int half = 0; half < 2; half++) {
                int r = row + half * 8;
                if (r < M) {
                    float2 o;
                    o.x = acc[i][j][half * 2 + 0] + bv.x;
                    o.y = acc[i][j][half * 2 + 1] + bv.y;
                    if (BLEND) {
                        float2 hv = *(const float2*)(Hres + (size_t)r * LDB + col);
                        o.x = o.x * alpha + hv.x * beta;
                        o.y = o.y * alpha + hv.y * beta;
                    }
                    *(float2*)(C + (size_t)r * LDB + col) = o;
                }
            }
        }
    }
}

// ---------------- init of per-node max / sum ----------------
__global__ void init_ms_kernel(float* __restrict__ nmax, float* __restrict__ nsum, int n)
{
    int i = blockIdx.x * blockDim.x + threadIdx.x;
    if (i < n) { nmax[i] = __int_as_float(0xff800000); nsum[i] = 0.f; }
}

// ---------------- edge pass A: attention scores + segment max ----------------
__global__ void edge_att_kernel(const float* __restrict__ q, const float* __restrict__ kvt,
                                const int* __restrict__ src, const int* __restrict__ dst,
                                const float* __restrict__ pri,
                                float* __restrict__ att, float* __restrict__ nmax, int E)
{
    int gid = blockIdx.x * blockDim.x + threadIdx.x;
    int e = gid >> 5;
    if (e >= E) return;
    int lane = gid & 31;
    int h = lane >> 2, g = lane & 3;
    int s = src[e], d = dst[e];
    const float4* qp = (const float4*)(q   + (size_t)d * 512  + h * 64 + g * 16);
    const float4* kp = (const float4*)(kvt + (size_t)s * 1024 + h * 64 + g * 16);
    float sum = 0.f;
#pragma unroll
    for (int t = 0; t < 4; t++) {
        float4 a = qp[t], b = kp[t];
        sum += a.x * b.x + a.y * b.y + a.z * b.z + a.w * b.w;
    }
    sum += __shfl_xor_sync(0xffffffffu, sum, 1);
    sum += __shfl_xor_sync(0xffffffffu, sum, 2);
    if (g == 0) {
        float a = sum * pri[h] * 0.125f;   // / sqrt(64)
        att[(size_t)e * HH + h] = a;
        atomicMaxF(&nmax[(size_t)d * HH + h], a);
    }
}

// ---------------- edge pass B: exp + segment sum ----------------
__global__ void edge_exp_kernel(const int* __restrict__ dst, float* __restrict__ att,
                                const float* __restrict__ nmax, float* __restrict__ nsum, int E)
{
    int i = blockIdx.x * blockDim.x + threadIdx.x;
    if (i >= E * HH) return;
    int e = i >> 3, h = i & 7;
    int d = dst[e];
    float ev = __expf(att[i] - nmax[(size_t)d * HH + h]);
    att[i] = ev;
    atomicAdd(&nsum[(size_t)d * HH + h], ev);
}

// ---------------- edge pass C: normalized weighted scatter ----------------
__global__ void edge_scatter_kernel(const float* __restrict__ kvt,
                                    const int* __restrict__ src, const int* __restrict__ dst,
                                    const float* __restrict__ att, const float* __restrict__ nsum,
                                    float* __restrict__ tbuf, int E)
{
    int gid = blockIdx.x * blockDim.x + threadIdx.x;
    int e = gid >> 5;
    if (e >= E) return;
    int lane = gid & 31;
    int h = lane >> 2, g = lane & 3;
    int s = src[e], d = dst[e];
    float a = att[(size_t)e * HH + h] / nsum[(size_t)d * HH + h];
    const float4* vp = (const float4*)(kvt + (size_t)s * 1024 + 512 + h * 64 + g * 16);
    float* tp = tbuf + (size_t)d * 512 + h * 64 + g * 16;
#pragma unroll
    for (int t = 0; t < 4; t++) {
        float4 v = vp[t];
        atomicAdd(tp + t * 4 + 0, a * v.x);
        atomicAdd(tp + t * 4 + 1, a * v.y);
        atomicAdd(tp + t * 4 + 2, a * v.z);
        atomicAdd(tp + t * 4 + 3, a * v.w);
    }
}

// ---------------- host launcher ----------------
extern "C" void kernel_launch(void* const* d_in, const int* in_sizes, int n_in,
                              void* d_out, int out_size)
{
    const float* h_paper  = (const float*)d_in[0];
    const float* h_author = (const float*)d_in[1];
    const int*   src0     = (const int*)d_in[2];
    const int*   dst0     = (const int*)d_in[3];
    const int*   src1     = (const int*)d_in[4];
    const int*   dst1     = (const int*)d_in[5];
    const float* Wk0 = (const float*)d_in[6];  const float* bk0 = (const float*)d_in[7];
    const float* Wq0 = (const float*)d_in[8];  const float* bq0 = (const float*)d_in[9];
    const float* Wv0 = (const float*)d_in[10]; const float* bv0 = (const float*)d_in[11];
    const float* Wa0 = (const float*)d_in[12]; const float* ba0 = (const float*)d_in[13];
    const float* Wk1 = (const float*)d_in[14]; const float* bk1 = (const float*)d_in[15];
    const float* Wq1 = (const float*)d_in[16]; const float* bq1 = (const float*)d_in[17];
    const float* Wv1 = (const float*)d_in[18]; const float* bv1 = (const float*)d_in[19];
    const float* Wa1 = (const float*)d_in[20]; const float* ba1 = (const float*)d_in[21];
    const float* rel_att = (const float*)d_in[22]; // [2,8,64,64]
    const float* rel_msg = (const float*)d_in[23];
    const float* rel_pri = (const float*)d_in[24]; // [2,8]
    const float* skip    = (const float*)d_in[25]; // [2]

    const int N = in_sizes[0] / 512;
    const int E = in_sizes[2];
    float* out = (float*)d_out;

    void *p_q, *p_kvt, *p_t, *p_Wf, *p_bf, *p_att, *p_max, *p_sum;
    cudaGetSymbolAddress(&p_q,   g_q);
    cudaGetSymbolAddress(&p_kvt, g_kvt);
    cudaGetSymbolAddress(&p_t,   g_t);
    cudaGetSymbolAddress(&p_Wf,  g_Wf);
    cudaGetSymbolAddress(&p_bf,  g_bf);
    cudaGetSymbolAddress(&p_att, g_att);
    cudaGetSymbolAddress(&p_max, g_max);
    cudaGetSymbolAddress(&p_sum, g_sum);
    float* qbuf  = (float*)p_q;
    float* kvt   = (float*)p_kvt;
    float* tbuf  = (float*)p_t;
    float* Wf    = (float*)p_Wf;
    float* bf    = (float*)p_bf;
    float* attb  = (float*)p_att;
    float* nmax  = (float*)p_max;
    float* nsum  = (float*)p_sum;

    const int relstrideT = HH * DKH * DKH; // 8*64*64
    const int gm = (N + 127) / 128;

    for (int rel = 0; rel < 2; rel++) {
        const float *Wk, *bk, *Wv, *bv, *Wq, *bq, *Wa, *ba;
        const float *hsrc, *hdst; const int *src, *dst;
        if (rel == 0) {
            Wk = Wk1; bk = bk1; Wv = Wv1; bv = bv1;
            Wq = Wq0; bq = bq0; Wa = Wa0; ba = ba0;
            hsrc = h_author; hdst = h_paper; src = src0; dst = dst0;
        } else {
            Wk = Wk0; bk = bk0; Wv = Wv0; bv = bv0;
            Wq = Wq1; bq = bq1; Wa = Wa1; ba = ba1;
            hsrc = h_paper; hdst = h_author; src = src1; dst = dst1;
        }
        const float* Arel = rel_att + (size_t)rel * relstrideT;
        const float* Mrel = rel_msg + (size_t)rel * relstrideT;
        const float* pri  = rel_pri + (size_t)rel * HH;
        float* outr = out + (size_t)rel * N * 512;

        // 1) fold relation transforms into weights
        fold_kernel<<<dim3(4, 513), 256>>>(Wk, bk, Wv, bv, Arel, Mrel, Wf, bf);

        // 2) kvt = h_src @ Wf + bf   ([N,1024])
        sgemm_tc<1024, false><<<dim3(8, gm), 256>>>(hsrc, Wf, bf, kvt, nullptr, nullptr, 0, N);

        // 3) q = h_dst @ Wq + bq   ([N,512])
        sgemm_tc<512, false><<<dim3(4, gm), 256>>>(hdst, Wq, bq, qbuf, nullptr, nullptr, 0, N);

        // 4) init aggregation buffers
        cudaMemsetAsync(tbuf, 0, (size_t)N * 512 * sizeof(float));
        init_ms_kernel<<<(N * HH + 255) / 256, 256>>>(nmax, nsum, N * HH);

        // 5) edge attention + segment max
        edge_att_kernel<<<(E * 32 + 255) / 256, 256>>>(qbuf, kvt, src, dst, pri, attb, nmax, E);
        // 6) exp + segment sum
        edge_exp_kernel<<<(E * HH + 255) / 256, 256>>>(dst, attb, nmax, nsum, E);
        // 7) weighted scatter of values
        edge_scatter_kernel<<<(E * 32 + 255) / 256, 256>>>(kvt, src, dst, attb, nsum, tbuf, E);

        // 8) out = (t @ Wa + ba) * sigmoid(skip) + h_dst * (1 - sigmoid(skip))
        sgemm_tc<512, true><<<dim3(4, gm), 256>>>(tbuf, Wa, ba, outr, hdst, skip, rel, N);
    }
}